// round 8
// baseline (speedup 1.0000x reference)
#include <cuda_runtime.h>
#include <cstdint>
#include <math.h>

#define NB 8
#define CIN 256
#define LL 1024

typedef unsigned long long u64;
typedef unsigned int u32;

// ---------------- f32x2 helpers (Blackwell packed fp32) ----------------
__device__ __forceinline__ u64 pack2(float x) {
    u64 r; u32 xi = __float_as_uint(x);
    asm("mov.b64 %0, {%1, %1};" : "=l"(r) : "r"(xi));
    return r;
}
__device__ __forceinline__ u64 packab(float a, float b) {
    u64 r;
    asm("mov.b64 %0, {%1, %2};" : "=l"(r) : "r"(__float_as_uint(a)), "r"(__float_as_uint(b)));
    return r;
}
__device__ __forceinline__ void fma2(u64& d, u64 a, u64 b) {
    asm("fma.rn.f32x2 %0, %1, %2, %0;" : "+l"(d) : "l"(a), "l"(b));
}
__device__ __forceinline__ u64 mul2(u64 a, u64 b) {
    u64 d; asm("mul.rn.f32x2 %0, %1, %2;" : "=l"(d) : "l"(a), "l"(b));
    return d;
}
__device__ __forceinline__ void unpack2(u64 v, float& lo, float& hi) {
    u32 l, h;
    asm("mov.b64 {%0, %1}, %2;" : "=r"(l), "=r"(h) : "l"(v));
    lo = __uint_as_float(l); hi = __uint_as_float(h);
}
// cp.async 16B with zero-fill predicate (src_size = 0 -> zeros)
__device__ __forceinline__ void cp16(u32 dst, const void* src, bool pred) {
    int sz = pred ? 16 : 0;
    asm volatile("cp.async.cg.shared.global [%0], [%1], 16, %2;\n"
                 :: "r"(dst), "l"(src), "r"(sz) : "memory");
}
__device__ __forceinline__ u32 sptr(const void* p) {
    return (u32)__cvta_generic_to_shared(p);
}

// scratch (static device globals; no allocation)
__device__ float g_k[NB*8*LL*8];
__device__ float g_q[NB*8*LL*8];
__device__ float g_v[NB*8*LL*8];
__device__ float g_attn[NB*LL*64];

// ---------------------------------------------------------------------------
// K1: qkv = x @ qkv_w + qkv_b  (8192 px, 256 -> 192), split heads into scratch
// ---------------------------------------------------------------------------
__global__ __launch_bounds__(192) void qkv_kernel(
    const float* __restrict__ x, const float* __restrict__ w,
    const float* __restrict__ bias)
{
    __shared__ float xs[16][CIN];
    int t = threadIdx.x;
    int blk = blockIdx.x;
    const float4* xg = (const float4*)(x + (size_t)blk * 16 * CIN);
    float4* xs4 = (float4*)xs;
    for (int idx = t; idx < 16 * CIN / 4; idx += 192) xs4[idx] = xg[idx];
    __syncthreads();

    float acc[16];
    float bv = bias[t];
#pragma unroll
    for (int p = 0; p < 16; p++) acc[p] = bv;

    for (int c = 0; c < CIN; c++) {
        float wv = __ldg(&w[c * 192 + t]);
#pragma unroll
        for (int p = 0; p < 16; p++) acc[p] = fmaf(xs[p][c], wv, acc[p]);
    }

    int sect = t >> 6;          // 0=k, 1=q, 2=v
    int cc = t & 63;
    int n = cc >> 3, d = cc & 7;
    float* dst = (sect == 0) ? g_k : ((sect == 1) ? g_q : g_v);
    float scale = (sect == 1) ? 0.35355339059327379f : 1.0f;  // DKH^-0.5
#pragma unroll
    for (int p = 0; p < 16; p++) {
        int gp = blk * 16 + p;
        int b = gp >> 10, i = gp & 1023;
        dst[(((size_t)(b * 8 + n) * LL + i) << 3) + d] = acc[p] * scale;
    }
}

// ---------------------------------------------------------------------------
// K2: attention. grid 512 = head*8 + qchunk ; block 128 (1 thread = 1 query)
// single-pass softmax without max-subtraction, f32x2 packed math.
// ---------------------------------------------------------------------------
__global__ __launch_bounds__(128) void attn_kernel(
    const float* __restrict__ krw_g, const float* __restrict__ krh_g)
{
    extern __shared__ float sm[];
    float* ksm = sm;              // 8192
    float* vsm = sm + 8192;       // 8192
    float* rw  = sm + 16384;      // 63*128 (pad to 8192)
    float* krw = sm + 24576;      // 512
    float* krh = sm + 25088;      // 512  -> total 25600 floats = 100 KB

    int t = threadIdx.x;
    int bid = blockIdx.x;
    int qc   = bid & 7;
    int head = bid >> 3;          // b*8+n
    int n = head & 7;
    int b = head >> 3;

    const float4* kg = (const float4*)(g_k + (size_t)head * 8192);
    const float4* vg = (const float4*)(g_v + (size_t)head * 8192);
    for (int idx = t; idx < 2048; idx += 128) {
        ((float4*)ksm)[idx] = kg[idx];
        ((float4*)vsm)[idx] = vg[idx];
    }
    for (int idx = t; idx < 504; idx += 128) { krw[idx] = krw_g[idx]; krh[idx] = krh_g[idx]; }
    __syncthreads();

    int i = qc * 128 + t;
    int yq = i & 31;
    int xq = i >> 5;
    float4 qa = *(const float4*)(g_q + (size_t)head * 8192 + i * 8);
    float4 qb = *(const float4*)(g_q + (size_t)head * 8192 + i * 8 + 4);
    u64 q01 = packab(qa.x, qa.y), q23 = packab(qa.z, qa.w);
    u64 q45 = packab(qb.x, qb.y), q67 = packab(qb.z, qb.w);

    for (int d = 0; d < 63; d++) {
        const float* r1 = krw + d * 8;
        float s1 = fmaf(qa.x, r1[0], fmaf(qa.y, r1[1], fmaf(qa.z, r1[2], qa.w * r1[3])))
                 + fmaf(qb.x, r1[4], fmaf(qb.y, r1[5], fmaf(qb.z, r1[6], qb.w * r1[7])));
        rw[d * 128 + t] = s1;
    }

    float s = 0.f;
    u64 a0 = 0ull, a1 = 0ull, a2 = 0ull, a3 = 0ull;
    const float* rwp = rw + (31 - yq) * 128 + t;
    const ulonglong2* k2p = (const ulonglong2*)ksm;
    const ulonglong2* v2p = (const ulonglong2*)vsm;

    for (int x2 = 0; x2 < 32; x2++) {
        const float* r2 = krh + (x2 - xq + 31) * 8;
        float rhv = fmaf(qa.x, r2[0], fmaf(qa.y, r2[1], fmaf(qa.z, r2[2], qa.w * r2[3])))
                  + fmaf(qb.x, r2[4], fmaf(qb.y, r2[5], fmaf(qb.z, r2[6], qb.w * r2[7])));
        int jb = x2 << 5;
#pragma unroll 8
        for (int y2 = 0; y2 < 32; y2++) {
            int j = jb + y2;
            ulonglong2 kA = k2p[2 * j];
            ulonglong2 kB = k2p[2 * j + 1];
            u64 d = mul2(q01, kA.x);
            fma2(d, q23, kA.y);
            fma2(d, q45, kB.x);
            fma2(d, q67, kB.y);
            float lo, hi; unpack2(d, lo, hi);
            float l = (lo + hi) + (rhv + rwp[y2 * 128]);
            float p = __expf(l);
            s += p;
            u64 pp = pack2(p);
            ulonglong2 vA = v2p[2 * j];
            ulonglong2 vB = v2p[2 * j + 1];
            fma2(a0, pp, vA.x); fma2(a1, pp, vA.y);
            fma2(a2, pp, vB.x); fma2(a3, pp, vB.y);
        }
    }
    float inv = 1.f / s;
    float o[8];
    unpack2(a0, o[0], o[1]); unpack2(a1, o[2], o[3]);
    unpack2(a2, o[4], o[5]); unpack2(a3, o[6], o[7]);
    float* op = g_attn + ((size_t)(b * LL + i)) * 64 + n * 8;
#pragma unroll
    for (int c = 0; c < 8; c++) op[c] = o[c] * inv;
}

// ---------------------------------------------------------------------------
// K3: out-proj 64x64 + bias, write channels [192,256) of output
// ---------------------------------------------------------------------------
__global__ __launch_bounds__(64) void proj_kernel(
    const float* __restrict__ aw, const float* __restrict__ ab,
    float* __restrict__ out)
{
    __shared__ float as[16][64];
    __shared__ float ws[64][64];
    int t = threadIdx.x;   // 64
    int blk = blockIdx.x;  // 512
    {
        const float4* wg = (const float4*)aw;
        float4* wd = (float4*)ws;
        for (int idx = t; idx < 1024; idx += 64) wd[idx] = wg[idx];
        const float4* ag = (const float4*)(g_attn + (size_t)blk * 16 * 64);
        float4* as4 = (float4*)as;
        for (int idx = t; idx < 256; idx += 64) as4[idx] = ag[idx];
    }
    __syncthreads();
    float acc[16];
    float bv = ab[t];
#pragma unroll
    for (int p = 0; p < 16; p++) acc[p] = bv;
    for (int c = 0; c < 64; c++) {
        float wv = ws[c][t];
#pragma unroll
        for (int p = 0; p < 16; p++) acc[p] = fmaf(as[p][c], wv, acc[p]);
    }
    for (int p = 0; p < 16; p++) {
        int gp = blk * 16 + p;
        out[(size_t)gp * 256 + 192 + t] = acc[p];
    }
}

// ---------------------------------------------------------------------------
// K4: 3x3 conv 256->192, SAME.  Crossbar-balanced version.
// grid 256 = b*32 + yp*2 + half (2 rows x 16 cols per block), 96 threads:
// 24 cout-groups (8 couts: 4cg..4cg+3 and 96+4cg..+3) x 4 px-groups (8 px:
// row pg>>1, cols (pg&1)*8..+7).  Thread tile 8 px x 8 couts -> per 4-cin
// group: 128 FFMA2 vs 8 dense weight LDS.128 (~24 wf) + 8 broadcast act
// LDS.128 (8 wf) = 32 wf against 64-cycle FMA budget -> FMA-bound.
// cp.async double-buffered staging (input zfill halo; weights per tap-chunk).
// 144 steps = 16 cin-chunks x 9 taps.
// ---------------------------------------------------------------------------
__global__ __launch_bounds__(96, 4) void conv_kernel(
    const float* __restrict__ x, const float* __restrict__ cw,
    const float* __restrict__ cb, float* __restrict__ out)
{
    __shared__ __align__(16) float in_t[2][1152];   // [4 rows][18 cols][16 cin]
    __shared__ __align__(16) float w_t[2][3072];    // [16 cin][192 cout]

    int t = threadIdx.x;           // 96
    int bid = blockIdx.x;
    int half = bid & 1;
    int yp = (bid >> 1) & 15;
    int b = bid >> 5;
    int x0 = half << 4;
    int y0 = yp << 1;

    int cg = t % 24;
    int pg = t / 24;               // 0..3
    int r  = pg >> 1;              // row 0..1
    int c8 = (pg & 1) << 3;        // col base 0 or 8
    int colo = cg << 2;            // couts colo..colo+3
    int cohi = 96 + colo;

    // ---- stage input chunk 0 + weight step 0 via cp.async ----
    {
#pragma unroll
        for (int k = 0; k < 3; k++) {
            int idx = t + k * 96;               // 0..287
            int f4  = idx & 3;
            int col = (idx >> 2) % 18;
            int row = (idx >> 2) / 18;
            int gy = y0 - 1 + row, gx = x0 - 1 + col;
            bool inb = ((unsigned)gy < 32u) && ((unsigned)gx < 32u);
            const float* src = inb ? (x + (((size_t)((b * 32 + gy) * 32 + gx)) << 8) + f4 * 4) : x;
            cp16(sptr(&in_t[0][(row * 18 + col) * 16 + f4 * 4]), src, inb);
        }
#pragma unroll
        for (int k = 0; k < 8; k++) {
            int j = t + k * 96;                 // 0..767 float4s
            cp16(sptr(&w_t[0][j * 4]), cw + j * 4, true);
        }
        asm volatile("cp.async.commit_group;" ::: "memory");
        asm volatile("cp.async.wait_group 0;" ::: "memory");
    }
    __syncthreads();

    u64 acc[8][4];
    {
        float4 cbl = *(const float4*)(cb + colo);
        float4 cbh = *(const float4*)(cb + cohi);
#pragma unroll
        for (int p = 0; p < 8; p++) {
            acc[p][0] = packab(cbl.x, cbl.y);
            acc[p][1] = packab(cbl.z, cbl.w);
            acc[p][2] = packab(cbh.x, cbh.y);
            acc[p][3] = packab(cbh.z, cbh.w);
        }
    }

    for (int s = 0; s < 144; s++) {
        int c16 = s / 9;
        int tap = s - 9 * c16;

        // ---- issue prefetch for step s+1 into the other buffers ----
        if (s < 143) {
            int ns = s + 1;
            int nc = ns / 9;
            int ntap = ns - 9 * nc;
            const float* wsrc = cw + ((size_t)(ntap * 256 + nc * 16)) * 192;
            float* wdst = w_t[ns & 1];
#pragma unroll
            for (int k = 0; k < 8; k++) {
                int j = t + k * 96;
                cp16(sptr(wdst + j * 4), wsrc + j * 4, true);
            }
            if (ntap == 0) {
                int cinb = nc * 16;
                float* idst = in_t[nc & 1];
#pragma unroll
                for (int k = 0; k < 3; k++) {
                    int idx = t + k * 96;
                    int f4  = idx & 3;
                    int col = (idx >> 2) % 18;
                    int row = (idx >> 2) / 18;
                    int gy = y0 - 1 + row, gx = x0 - 1 + col;
                    bool inb = ((unsigned)gy < 32u) && ((unsigned)gx < 32u);
                    const float* src = inb ? (x + (((size_t)((b * 32 + gy) * 32 + gx)) << 8) + cinb + f4 * 4) : x;
                    cp16(sptr(idst + (row * 18 + col) * 16 + f4 * 4), src, inb);
                }
            }
            asm volatile("cp.async.commit_group;" ::: "memory");
        }

        // ---- compute step s ----
        int ky = tap / 3, kx = tap - ky * 3;
        const float* ap = &in_t[c16 & 1][((r + ky) * 18 + c8 + kx) * 16];
        const float* wp = w_t[s & 1];
#pragma unroll
        for (int cc = 0; cc < 16; cc += 4) {
            float A[8][4];
#pragma unroll
            for (int p = 0; p < 8; p++) {
                float4 tmp = *(const float4*)(ap + p * 16 + cc);
                A[p][0] = tmp.x; A[p][1] = tmp.y; A[p][2] = tmp.z; A[p][3] = tmp.w;
            }
#pragma unroll
            for (int u = 0; u < 4; u++) {
                const float* wr = wp + (cc + u) * 192;
                ulonglong2 wl = *(const ulonglong2*)(wr + colo);
                ulonglong2 wh = *(const ulonglong2*)(wr + cohi);
#pragma unroll
                for (int p = 0; p < 8; p++) {
                    u64 av = pack2(A[p][u]);
                    fma2(acc[p][0], av, wl.x);
                    fma2(acc[p][1], av, wl.y);
                    fma2(acc[p][2], av, wh.x);
                    fma2(acc[p][3], av, wh.y);
                }
            }
        }

        if (s < 143) asm volatile("cp.async.wait_group 0;" ::: "memory");
        __syncthreads();
    }

    // ---- epilogue: 8 px x 8 couts per thread ----
#pragma unroll
    for (int p = 0; p < 8; p++) {
        int gx = x0 + c8 + p;
        float* op = out + (((size_t)((b * 32 + y0 + r) * 32 + gx)) << 8);
        float o0, o1, o2, o3;
        unpack2(acc[p][0], o0, o1); unpack2(acc[p][1], o2, o3);
        *(float4*)(op + colo) = make_float4(o0, o1, o2, o3);
        unpack2(acc[p][2], o0, o1); unpack2(acc[p][3], o2, o3);
        *(float4*)(op + cohi) = make_float4(o0, o1, o2, o3);
    }
}

// ---------------------------------------------------------------------------
extern "C" void kernel_launch(void* const* d_in, const int* in_sizes, int n_in,
                              void* d_out, int out_size)
{
    const float* x      = (const float*)d_in[0];
    const float* conv_w = (const float*)d_in[1];
    const float* conv_b = (const float*)d_in[2];
    const float* qkv_w  = (const float*)d_in[3];
    const float* qkv_b  = (const float*)d_in[4];
    const float* attn_w = (const float*)d_in[5];
    const float* attn_b = (const float*)d_in[6];
    const float* krw    = (const float*)d_in[7];
    const float* krh    = (const float*)d_in[8];
    float* out = (float*)d_out;

    // one-time resources (host-side handles only; no device allocations)
    static cudaStream_t s2 = nullptr;
    static cudaEvent_t efork = nullptr, ejoin = nullptr;
    if (s2 == nullptr) {
        cudaStreamCreateWithFlags(&s2, cudaStreamNonBlocking);
        cudaEventCreateWithFlags(&efork, cudaEventDisableTiming);
        cudaEventCreateWithFlags(&ejoin, cudaEventDisableTiming);
    }
    cudaFuncSetAttribute(attn_kernel, cudaFuncAttributeMaxDynamicSharedMemorySize, 102400);

    // fork: attention chain on s2, conv on the main stream (disjoint outputs)
    cudaEventRecord(efork, 0);
    cudaStreamWaitEvent(s2, efork, 0);

    qkv_kernel<<<512, 192, 0, s2>>>(x, qkv_w, qkv_b);
    attn_kernel<<<512, 128, 102400, s2>>>(krw, krh);
    proj_kernel<<<512, 64, 0, s2>>>(attn_w, attn_b, out);
    cudaEventRecord(ejoin, s2);

    conv_kernel<<<256, 96>>>(x, conv_w, conv_b, out);

    // join
    cudaStreamWaitEvent(0, ejoin, 0);
}